// round 15
// baseline (speedup 1.0000x reference)
#include <cuda_runtime.h>
#include <cuda_bf16.h>
#include <cstdint>
#include <cstdio>

// ---------------- static config ----------------
#define N_NOTES 1024
#define IN_SIZE 78
#define NOTE_H 256
#define MEAS_H 256
#define GSIZE 768
#define N_EDGE 8
#define N_HEAD 8
#define ATT_D 512
#define N_MEAS 64
#define KGATE 6144   // N_EDGE * GSIZE
#define KGATE_C 2048 // N_EDGE * 256 (compacted, g1-it1)
#define ADJ_CAP 96

// ---------------- scratch (device global; no allocs allowed) ----------------
#define OFF_H      0u
#define OFF_H1     786432u
#define OFF_G      1572864u
#define OFF_Z      3932160u
#define OFF_CAT    4718592u
#define OFF_A      5242880u
#define OFF_MN     5767168u
#define OFF_XPROJ  5799936u
#define OFF_XB1    5931008u
#define OFF_XB2    5963776u
#define OFF_SB     5996544u
#define OFF_ACT_H  6000640u
#define OFF_ACT_L  9146368u
#define OFF_HR_H   12292096u
#define OFF_HR_L   12685312u
#define OFF_RH_H   13078528u
#define OFF_RH_L   13471744u
#define OFF_WT_H   13864960u   // set 0 (g1): wT [3][768][6144]
#define OFF_WT_L   20942848u
#define OFF_UT_H   28020736u   // set 0 (g1): uT [3][768][768]
#define OFF_UT_L   28905472u
#define OFF_WT2_H  29790208u   // set 1 (g2)
#define OFF_WT2_L  36868096u
#define OFF_UT2_H  43945984u
#define OFF_UT2_L  44830720u
#define OFF_WTC_H  45715456u   // compacted wT set0: [3][768][2048]
#define OFF_WTC_L  48074752u
#define SCRATCH_FLOATS 50434048u

__device__ float g_scratch[SCRATCH_FLOATS];
__device__ int g_adj_cnt[N_EDGE * N_NOTES];
__device__ int g_adj_list[N_EDGE * N_NOTES * ADJ_CAP];

// LSTM cross-block sync state (per layer, per dir)
__device__ unsigned int g_lstm_cnt[2][2];
__device__ float g_hbuf[2][2][2][256];   // [layer][dir][parity][256]

__device__ __forceinline__ float sigmoidf_(float x) { return 1.0f / (1.0f + expf(-x)); }

__device__ __forceinline__ void bfsplit(float v, __nv_bfloat16* H, __nv_bfloat16* L, size_t idx) {
    __nv_bfloat16 h = __float2bfloat16(v);
    H[idx] = h;
    L[idx] = __float2bfloat16(v - __bfloat162float(h));
}

// ---- packed f32x2 helpers (fp32 FFMA2 path for NT gemms) ----
__device__ __forceinline__ unsigned long long pack2(float x, float y) {
    unsigned long long r;
    asm("mov.b64 %0, {%1, %2};" : "=l"(r) : "r"(__float_as_uint(x)), "r"(__float_as_uint(y)));
    return r;
}
__device__ __forceinline__ float2 unpack2(unsigned long long v) {
    unsigned int lo, hi;
    asm("mov.b64 {%0, %1}, %2;" : "=r"(lo), "=r"(hi) : "l"(v));
    return make_float2(__uint_as_float(lo), __uint_as_float(hi));
}
#define FFMA2(d, a, b) asm("fma.rn.f32x2 %0, %1, %2, %0;" : "+l"(d) : "l"(a), "l"(b))

// ---- tensor-core helpers (legacy mma.sync — tcgen05 unavailable at compute_103) ----
#define MMA_BF16(d, a, b0, b1) asm volatile( \
    "mma.sync.aligned.m16n8k16.row.col.f32.bf16.bf16.f32 " \
    "{%0,%1,%2,%3}, {%4,%5,%6,%7}, {%8,%9}, {%0,%1,%2,%3};" \
    : "+f"((d)[0]), "+f"((d)[1]), "+f"((d)[2]), "+f"((d)[3]) \
    : "r"((a)[0]), "r"((a)[1]), "r"((a)[2]), "r"((a)[3]), "r"(b0), "r"(b1))

#define LDSM4(r, addr) asm volatile( \
    "ldmatrix.sync.aligned.m8n8.x4.shared.b16 {%0,%1,%2,%3}, [%4];" \
    : "=r"((r)[0]), "=r"((r)[1]), "=r"((r)[2]), "=r"((r)[3]) : "r"(addr))

#define CP16(dst, src) asm volatile( \
    "cp.async.ca.shared.global [%0], [%1], 16;" :: "r"(dst), "l"(src))
#define CP_COMMIT() asm volatile("cp.async.commit_group;")
#define CP_WAIT2()  asm volatile("cp.async.wait_group 2;")
#define CP_WAIT0()  asm volatile("cp.async.wait_group 0;")

// ================= bf16-split tensor GEMM (128x128 tile, 4-stage) =================
// C[z] = A1 @ B1[z] (+ A2 @ B2[z] if z < zA2limit) (+C if beta), fp32 accumulate.
// Optional fused ew2 epilogue (beta call): instead of writing C, computes
// h = z*h + (1-z)*tanh(acc + Cold + b2) elementwise and writes h + bf16 split.
#define BPITCH 40
#define STG_BF (128 * BPITCH)
#define NSTAGE 4
#define GEMM_SMEM (NSTAGE * 4 * STG_BF * 2)   // 163840 bytes

__global__ __launch_bounds__(256) void gemm_bf16s_kernel(
    const __nv_bfloat16* __restrict__ A1h, const __nv_bfloat16* __restrict__ A1l, int lda1,
    const __nv_bfloat16* __restrict__ B1h, const __nv_bfloat16* __restrict__ B1l,
    long b1stride, int ldb1,
    const __nv_bfloat16* __restrict__ A2h, const __nv_bfloat16* __restrict__ A2l, int lda2,
    const __nv_bfloat16* __restrict__ B2h, const __nv_bfloat16* __restrict__ B2l,
    long b2stride, int ldb2, int zA2limit,
    float* __restrict__ Cbase, long cstride, int ldc,
    int K1, int K2, int beta,
    const float* __restrict__ ewb2,          // non-null => fused ew2 epilogue
    float* __restrict__ Hp,
    __nv_bfloat16* __restrict__ HRh, __nv_bfloat16* __restrict__ HRl)
{
    extern __shared__ __nv_bfloat16 smb[];
    const int tid = threadIdx.x, lane = tid & 31, wid = tid >> 5;
    const int z = blockIdx.z;
    const int row0 = blockIdx.y * 128, col0 = blockIdx.x * 128;
    const int m0 = (wid >> 1) * 32, n0w = (wid & 1) * 64;
    float* C = Cbase + (long)z * cstride;
    const bool use2 = (z < zA2limit) && (K2 > 0);

    float acc[2][8][4];
#pragma unroll
    for (int i = 0; i < 2; i++)
#pragma unroll
        for (int j = 0; j < 8; j++)
#pragma unroll
            for (int k = 0; k < 4; k++) acc[i][j][k] = 0.0f;

    const uint32_t smu = (uint32_t)__cvta_generic_to_shared(smb);

    const int srow = tid >> 1;
    const int skoff = (tid & 1) * 16;

    const int lRow = lane & 15;
    const int lOff8 = ((lane >> 4) & 1) * 8;

    auto pipeline = [&](const __nv_bfloat16* Ah, const __nv_bfloat16* Al, int lda,
                        const __nv_bfloat16* Bh, const __nv_bfloat16* Bl, int ldb, int K) {
        const int ns = K >> 5;
        auto copy_stage = [&](int st, int kpos) {
            const __nv_bfloat16* sAh = Ah + (size_t)(row0 + srow) * lda + kpos + skoff;
            const __nv_bfloat16* sAl = Al + (size_t)(row0 + srow) * lda + kpos + skoff;
            const __nv_bfloat16* sBh = Bh + (size_t)(col0 + srow) * ldb + kpos + skoff;
            const __nv_bfloat16* sBl = Bl + (size_t)(col0 + srow) * ldb + kpos + skoff;
            const uint32_t rb = (uint32_t)(srow * BPITCH + skoff) * 2;
            uint32_t d0 = smu + (uint32_t)((st * 4 + 0) * STG_BF * 2) + rb;
            uint32_t d1 = smu + (uint32_t)((st * 4 + 1) * STG_BF * 2) + rb;
            uint32_t d2 = smu + (uint32_t)((st * 4 + 2) * STG_BF * 2) + rb;
            uint32_t d3 = smu + (uint32_t)((st * 4 + 3) * STG_BF * 2) + rb;
            CP16(d0, sAh); CP16(d0 + 16, sAh + 8);
            CP16(d1, sAl); CP16(d1 + 16, sAl + 8);
            CP16(d2, sBh); CP16(d2 + 16, sBh + 8);
            CP16(d3, sBl); CP16(d3 + 16, sBl + 8);
        };
        copy_stage(0, 0); CP_COMMIT();
        if (ns > 1) copy_stage(1, 32);
        CP_COMMIT();
        for (int s = 0; s < ns; s++) {
            if (s + 2 < ns) copy_stage((s + 2) & (NSTAGE - 1), (s + 2) * 32);
            CP_COMMIT();
            CP_WAIT2();
            __syncthreads();
            const int st = s & (NSTAGE - 1);
            const uint32_t aH = smu + (uint32_t)((st * 4 + 0) * STG_BF * 2);
            const uint32_t aL = smu + (uint32_t)((st * 4 + 1) * STG_BF * 2);
            const uint32_t bH = smu + (uint32_t)((st * 4 + 2) * STG_BF * 2);
            const uint32_t bL = smu + (uint32_t)((st * 4 + 3) * STG_BF * 2);
#pragma unroll
            for (int kh = 0; kh < 32; kh += 16) {
                uint32_t afh[2][4], afl[2][4];
#pragma unroll
                for (int mt = 0; mt < 2; mt++) {
                    const uint32_t off =
                        (uint32_t)(((m0 + mt * 16 + lRow) * BPITCH + kh + lOff8) * 2);
                    LDSM4(afh[mt], aH + off);
                    LDSM4(afl[mt], aL + off);
                }
                uint32_t bfh[4][4], bfl[4][4];
#pragma unroll
                for (int q = 0; q < 4; q++) {
                    const uint32_t off =
                        (uint32_t)(((n0w + q * 16 + lRow) * BPITCH + kh + lOff8) * 2);
                    LDSM4(bfh[q], bH + off);
                    LDSM4(bfl[q], bL + off);
                }
#pragma unroll
                for (int mt = 0; mt < 2; mt++)
#pragma unroll
                    for (int q = 0; q < 4; q++) {
                        MMA_BF16(acc[mt][2 * q], afl[mt], bfh[q][0], bfh[q][2]);
                        MMA_BF16(acc[mt][2 * q], afh[mt], bfl[q][0], bfl[q][2]);
                        MMA_BF16(acc[mt][2 * q], afh[mt], bfh[q][0], bfh[q][2]);
                        MMA_BF16(acc[mt][2 * q + 1], afl[mt], bfh[q][1], bfh[q][3]);
                        MMA_BF16(acc[mt][2 * q + 1], afh[mt], bfl[q][1], bfl[q][3]);
                        MMA_BF16(acc[mt][2 * q + 1], afh[mt], bfh[q][1], bfh[q][3]);
                    }
            }
            __syncthreads();
        }
        CP_WAIT0();
        __syncthreads();
    };

    pipeline(A1h, A1l, lda1, B1h + (long)z * b1stride, B1l + (long)z * b1stride, ldb1, K1);
    if (use2)
        pipeline(A2h, A2l, lda2, B2h + (long)z * b2stride, B2l + (long)z * b2stride, ldb2, K2);

    // epilogue
    const int r = lane >> 2, cb = 2 * (lane & 3);

    auto fuse_ew2 = [&](int row, int col, float a0, float a1) {
        float2 old = *reinterpret_cast<float2*>(C + (size_t)row * ldc + col);
        float g20 = a0 + old.x;
        float g21 = a1 + old.y;
        const size_t i0 = (size_t)row * GSIZE + col;
        float ht0 = tanhf(g20 + ewb2[col]);
        float ht1 = tanhf(g21 + ewb2[col + 1]);
        float z0 = g_scratch[OFF_Z + i0], z1 = g_scratch[OFF_Z + i0 + 1];
        float v0 = z0 * Hp[i0] + (1.0f - z0) * ht0;
        float v1 = z1 * Hp[i0 + 1] + (1.0f - z1) * ht1;
        Hp[i0] = v0; Hp[i0 + 1] = v1;
        bfsplit(v0, HRh, HRl, i0);
        bfsplit(v1, HRh, HRl, i0 + 1);
    };

#pragma unroll
    for (int mt = 0; mt < 2; mt++)
#pragma unroll
        for (int nt = 0; nt < 8; nt++) {
            const int col = col0 + n0w + nt * 8 + cb;
            const int rA = row0 + m0 + mt * 16 + r;
            if (ewb2) {
                fuse_ew2(rA, col, acc[mt][nt][0], acc[mt][nt][1]);
                fuse_ew2(rA + 8, col, acc[mt][nt][2], acc[mt][nt][3]);
            } else {
                float* p0 = C + (size_t)rA * ldc + col;
                float* p1 = C + (size_t)(rA + 8) * ldc + col;
                float2 v0 = make_float2(acc[mt][nt][0], acc[mt][nt][1]);
                float2 v1 = make_float2(acc[mt][nt][2], acc[mt][nt][3]);
                if (beta) {
                    float2 o0 = *reinterpret_cast<float2*>(p0);
                    float2 o1 = *reinterpret_cast<float2*>(p1);
                    v0.x += o0.x; v0.y += o0.y; v1.x += o1.x; v1.y += o1.y;
                }
                *reinterpret_cast<float2*>(p0) = v0;
                *reinterpret_cast<float2*>(p1) = v1;
            }
        }
}

// ---------------- merged transposes (bf16-split): w slabs (z<48) + u slabs ----------------
__global__ __launch_bounds__(256) void transpose_wu_kernel(
    const float* __restrict__ w1, const float* __restrict__ w2,
    const float* __restrict__ u1, const float* __restrict__ u2)
{
    __shared__ float t[32][33];
    const int zz = blockIdx.z;
    const int s0 = blockIdx.y * 32, n0 = blockIdx.x * 32;
    const int tx = threadIdx.x, ty = threadIdx.y;

    if (zz < 48) {
        const int set = zz / 24, zr = zz % 24;
        const float* w = set ? w2 : w1;
        const int g = zr >> 3, e = zr & 7;
        const float* src = w + ((size_t)(g * 8 + e) * 768 + s0) * 768 + n0;
#pragma unroll
        for (int i = 0; i < 32; i += 8) t[ty + i][tx] = src[(size_t)(ty + i) * 768 + tx];
        __syncthreads();
        __nv_bfloat16* H = reinterpret_cast<__nv_bfloat16*>(g_scratch + (set ? OFF_WT2_H : OFF_WT_H));
        __nv_bfloat16* L = reinterpret_cast<__nv_bfloat16*>(g_scratch + (set ? OFF_WT2_L : OFF_WT_L));
        __nv_bfloat16* HC = reinterpret_cast<__nv_bfloat16*>(g_scratch + OFF_WTC_H);
        __nv_bfloat16* LC = reinterpret_cast<__nv_bfloat16*>(g_scratch + OFF_WTC_L);
        const size_t base = (size_t)g * 768 * 6144 + (size_t)n0 * 6144 + e * 768 + s0;
        const bool compact = (set == 0) && (s0 >= 512);
        const size_t cbase = (size_t)g * 768 * KGATE_C + (size_t)n0 * KGATE_C + e * 256 + (s0 - 512);
#pragma unroll
        for (int i = 0; i < 32; i += 8) {
            float v = t[tx][ty + i];
            bfsplit(v, H, L, base + (size_t)(ty + i) * 6144 + tx);
            if (compact)
                bfsplit(v, HC, LC, cbase + (size_t)(ty + i) * KGATE_C + tx);
        }
    } else {
        const int zu = zz - 48;
        const int set = zu / 3, g = zu % 3;
        const float* u = set ? u2 : u1;
        const float* src = u + ((size_t)g * 768 + s0) * 768 + n0;
#pragma unroll
        for (int i = 0; i < 32; i += 8) t[ty + i][tx] = src[(size_t)(ty + i) * 768 + tx];
        __syncthreads();
        __nv_bfloat16* H = reinterpret_cast<__nv_bfloat16*>(g_scratch + (set ? OFF_UT2_H : OFF_UT_H));
        __nv_bfloat16* L = reinterpret_cast<__nv_bfloat16*>(g_scratch + (set ? OFF_UT2_L : OFF_UT_L));
        const size_t base = (size_t)g * 768 * 768 + (size_t)n0 * 768 + s0;
#pragma unroll
        for (int i = 0; i < 32; i += 8)
            bfsplit(t[tx][ty + i], H, L, base + (size_t)(ty + i) * 768 + tx);
    }
}

// ---------------- GEMM NT (C = act(A @ B^T + bias)), fp32 FFMA2, z-batched ----------------
__global__ __launch_bounds__(256) void gemm_nt_kernel(
    const float* __restrict__ Abase, int lda, long aBS,
    const float* __restrict__ Bbase, long bBS,
    const float* __restrict__ biasbase, long biasBS,
    float* __restrict__ Cbase, int ldc, long cBS,
    __nv_bfloat16* __restrict__ CrH, __nv_bfloat16* __restrict__ CrL,
    int M, int N, int K, int act)
{
    const int tid = threadIdx.x;
    const int z = blockIdx.z;
    const float* A = Abase + (long)z * aBS;
    const float* B = Bbase + (long)z * bBS;
    const float* bias = biasbase + (long)z * biasBS;
    float* C = Cbase + (long)z * cBS;

    __shared__ float As[8][128];
    __shared__ float Bs[8][128];

    const int row0 = blockIdx.y * 128;
    const int col0 = blockIdx.x * 128;
    const int tx = tid & 15, ty = tid >> 4;
    const int arow = tid >> 1, ak = (tid & 1) * 4;
    const int bnr = tid >> 1, bk = (tid & 1) * 4;

    unsigned long long acc[2][2][8];
#pragma unroll
    for (int h = 0; h < 2; h++)
#pragma unroll
        for (int p = 0; p < 2; p++)
#pragma unroll
            for (int c = 0; c < 8; c++) acc[h][p][c] = 0ULL;

    for (int k0 = 0; k0 < K; k0 += 8) {
        const int garow = row0 + arow;
#pragma unroll
        for (int t = 0; t < 4; t++) {
            int k = k0 + ak + t;
            As[ak + t][arow] = (garow < M && k < K) ? A[(size_t)garow * lda + k] : 0.0f;
        }
#pragma unroll
        for (int t = 0; t < 4; t++) {
            int k = k0 + bk + t;
            Bs[bk + t][bnr] = (k < K) ? B[(size_t)(col0 + bnr) * K + k] : 0.0f;
        }
        __syncthreads();
#pragma unroll
        for (int kk = 0; kk < 8; kk++) {
            ulonglong2 a0 = *reinterpret_cast<ulonglong2*>(&As[kk][ty * 4]);
            ulonglong2 a1 = *reinterpret_cast<ulonglong2*>(&As[kk][64 + ty * 4]);
            float4 blo = *reinterpret_cast<float4*>(&Bs[kk][tx * 4]);
            float4 bhi = *reinterpret_cast<float4*>(&Bs[kk][64 + tx * 4]);
            unsigned long long bb[8];
            bb[0] = pack2(blo.x, blo.x); bb[1] = pack2(blo.y, blo.y);
            bb[2] = pack2(blo.z, blo.z); bb[3] = pack2(blo.w, blo.w);
            bb[4] = pack2(bhi.x, bhi.x); bb[5] = pack2(bhi.y, bhi.y);
            bb[6] = pack2(bhi.z, bhi.z); bb[7] = pack2(bhi.w, bhi.w);
#pragma unroll
            for (int c = 0; c < 8; c++) {
                FFMA2(acc[0][0][c], a0.x, bb[c]);
                FFMA2(acc[0][1][c], a0.y, bb[c]);
                FFMA2(acc[1][0][c], a1.x, bb[c]);
                FFMA2(acc[1][1][c], a1.y, bb[c]);
            }
        }
        __syncthreads();
    }

#pragma unroll
    for (int hr = 0; hr < 2; hr++)
#pragma unroll
        for (int pr = 0; pr < 2; pr++)
#pragma unroll
            for (int sub = 0; sub < 2; sub++) {
                const int row = row0 + hr * 64 + ty * 4 + pr * 2 + sub;
                if (row >= M) continue;
#pragma unroll
                for (int half = 0; half < 2; half++) {
                    const int colb = col0 + half * 64 + tx * 4;
                    float* cp = C + (size_t)row * ldc + colb;
#pragma unroll
                    for (int c = 0; c < 4; c++) {
                        float2 f2 = unpack2(acc[hr][pr][half * 4 + c]);
                        float v = (sub ? f2.y : f2.x) + bias[colb + c];
                        if (act == 1) v = fmaxf(v, 0.0f);
                        else if (act == 2) v = tanhf(v);
                        cp[c] = v;
                        if (CrH) bfsplit(v, CrH, CrL, (size_t)row * ldc + colb + c);
                    }
                }
            }
}

// ---------------- adjacency CSR precompute ----------------
__global__ __launch_bounds__(256) void build_adj_kernel(const float* __restrict__ A)
{
    const int n = blockIdx.x * 256 + threadIdx.x;
    const int e = blockIdx.y;
    const float* col = A + (size_t)e * N_NOTES * N_NOTES + n;
    int cnt = 0;
    int* list = g_adj_list + ((size_t)e * N_NOTES + n) * ADJ_CAP;
#pragma unroll 8
    for (int m = 0; m < N_NOTES; m++) {
        float v = col[(size_t)m * N_NOTES];
        if (v != 0.0f) { if (cnt < ADJ_CAP) list[cnt] = m; cnt++; }
    }
    g_adj_cnt[e * N_NOTES + n] = min(cnt, ADJ_CAP);
}

// ---------------- sparse act (bf16-split output), full width ----------------
__global__ __launch_bounds__(256) void act_gather_kernel()
{
    const int n = blockIdx.x;
    const int tid = threadIdx.x;
    const float* h = g_scratch + OFF_H;
    __nv_bfloat16* AH = reinterpret_cast<__nv_bfloat16*>(g_scratch + OFF_ACT_H);
    __nv_bfloat16* AL = reinterpret_cast<__nv_bfloat16*>(g_scratch + OFF_ACT_L);
    const size_t base = (size_t)n * KGATE;
    __shared__ int lst[ADJ_CAP];
    for (int e = 0; e < N_EDGE; e++) {
        const int cnt = g_adj_cnt[e * N_NOTES + n];
        if (tid < cnt) lst[tid] = g_adj_list[((size_t)e * N_NOTES + n) * ADJ_CAP + tid];
        __syncthreads();
        float a0 = 0.f, a1 = 0.f, a2 = 0.f;
        for (int i = 0; i < cnt; i++) {
            const float* hr = h + (size_t)lst[i] * GSIZE;
            a0 += hr[tid]; a1 += hr[tid + 256]; a2 += hr[tid + 512];
        }
        bfsplit(a0, AH, AL, base + e * GSIZE + tid);
        bfsplit(a1, AH, AL, base + e * GSIZE + 256 + tid);
        bfsplit(a2, AH, AL, base + e * GSIZE + 512 + tid);
        __syncthreads();
    }
}

// compacted variant for g1-it1: only h cols [512,768) are nonzero; writes [1024][2048]
__global__ __launch_bounds__(256) void act_gather_compact_kernel()
{
    const int n = blockIdx.x;
    const int tid = threadIdx.x;
    const float* h = g_scratch + OFF_H;
    __nv_bfloat16* AH = reinterpret_cast<__nv_bfloat16*>(g_scratch + OFF_ACT_H);
    __nv_bfloat16* AL = reinterpret_cast<__nv_bfloat16*>(g_scratch + OFF_ACT_L);
    const size_t base = (size_t)n * KGATE_C;
    __shared__ int lst[ADJ_CAP];
    for (int e = 0; e < N_EDGE; e++) {
        const int cnt = g_adj_cnt[e * N_NOTES + n];
        if (tid < cnt) lst[tid] = g_adj_list[((size_t)e * N_NOTES + n) * ADJ_CAP + tid];
        __syncthreads();
        float a = 0.f;
        for (int i = 0; i < cnt; i++)
            a += h[(size_t)lst[i] * GSIZE + 512 + tid];
        bfsplit(a, AH, AL, base + e * 256 + tid);
        __syncthreads();
    }
}

// ---------------- gated-graph elementwise (ew1 only; ew2 fused into beta GEMM) --------
__global__ __launch_bounds__(256) void ew1_kernel(const float* __restrict__ b)
{
    const int i = blockIdx.x * 256 + threadIdx.x;
    const int s = i % GSIZE;
    const float* G = g_scratch + OFF_G;
    const float* h = g_scratch + OFF_H;
    float zz = sigmoidf_(G[i] + b[s]);
    float rr = sigmoidf_(G[N_NOTES * GSIZE + i] + b[GSIZE + s]);
    g_scratch[OFF_Z + i] = zz;
    bfsplit(rr * h[i],
            reinterpret_cast<__nv_bfloat16*>(g_scratch + OFF_RH_H),
            reinterpret_cast<__nv_bfloat16*>(g_scratch + OFF_RH_L), i);
}

// ---------------- cat = [h1[:,512:768] | h2[:,512:768]] ----------------
__global__ __launch_bounds__(512) void cat_kernel()
{
    const int n = blockIdx.x, c = threadIdx.x;
    const float* h1 = g_scratch + OFF_H1;
    const float* h2 = g_scratch + OFF_H;
    g_scratch[OFF_CAT + n * ATT_D + c] =
        (c < 256) ? h1[(size_t)n * GSIZE + 512 + c]
                  : h2[(size_t)n * GSIZE + 512 + (c - 256)];
}

// ---------------- measure attention pooling ----------------
__global__ __launch_bounds__(256) void att_pool_kernel(
    const float* __restrict__ cv, const int* __restrict__ mnum)
{
    const int m = blockIdx.x;
    const int tid = threadIdx.x;
    const float* a = g_scratch + OFF_A;
    const float* x = g_scratch + OFF_CAT;
    __shared__ int list[64];
    __shared__ int cnt;
    __shared__ float s_sh[64][8];
    __shared__ float hmax[8], hden[8];
    if (tid == 0) cnt = 0;
    __syncthreads();
    const int mn0 = mnum[0];
    for (int n = tid; n < N_NOTES; n += 256) {
        if (mnum[n] - mn0 == m) {
            int p = atomicAdd(&cnt, 1);
            if (p < 64) list[p] = n;
        }
    }
    __syncthreads();
    const int c = min(cnt, 64);
    const int w = tid >> 5, lane = tid & 31;
    for (int i = w; i < c; i += 8) {
        const float* ar = a + (size_t)list[i] * ATT_D;
#pragma unroll
        for (int h = 0; h < 8; h++) {
            float p = ar[h * 64 + lane] * cv[h * 64 + lane]
                    + ar[h * 64 + 32 + lane] * cv[h * 64 + 32 + lane];
            p += __shfl_xor_sync(0xffffffffu, p, 16);
            p += __shfl_xor_sync(0xffffffffu, p, 8);
            p += __shfl_xor_sync(0xffffffffu, p, 4);
            p += __shfl_xor_sync(0xffffffffu, p, 2);
            p += __shfl_xor_sync(0xffffffffu, p, 1);
            if (lane == 0) s_sh[i][h] = p;
        }
    }
    __syncthreads();
    if (tid < 8) {
        float mx = -1e30f;
        for (int i = 0; i < c; i++) mx = fmaxf(mx, s_sh[i][tid]);
        float den = 0.f;
        for (int i = 0; i < c; i++) den += expf(s_sh[i][tid] - mx);
        hmax[tid] = mx; hden[tid] = den;
    }
    __syncthreads();
    for (int col = tid; col < ATT_D; col += 256) {
        const int h = col >> 6;
        float pool = 0.f;
        for (int i = 0; i < c; i++) {
            float wgt = expf(s_sh[i][h] - hmax[h]) / hden[h];
            pool += wgt * x[(size_t)list[i] * ATT_D + col];
        }
        g_scratch[OFF_MN + m * ATT_D + col] = pool;
    }
}

// ---------------- misc init: sumbias + LSTM state ----------------
__global__ __launch_bounds__(256) void misc_init_kernel(const float* __restrict__ bih,
                                                        const float* __restrict__ bhh)
{
    const int i = blockIdx.x * 256 + threadIdx.x;
    g_scratch[OFF_SB + i] = bih[i] + bhh[i];
    if (blockIdx.x == 0) {
        if (threadIdx.x < 4) (&g_lstm_cnt[0][0])[threadIdx.x] = 0u;
        float* p = &g_hbuf[0][0][0][0];
        for (int k = threadIdx.x; k < 2048; k += 256) p[k] = 0.0f;
    }
}

__global__ __launch_bounds__(256) void lstm_rec_kernel(
    const float* __restrict__ Whh_layer,   // [2][1024][256]
    float* __restrict__ out, int layer)    // [64][512]
{
    const int b = blockIdx.x;
    const int dir = blockIdx.y;
    const int tid = threadIdx.x;
    const int r = tid >> 2;
    const int kq = tid & 3;
    const int seg = r >> 4, jj = r & 15;
    const int grow = seg * 256 + b * 16 + jj;

    __shared__ float hsh[256];
    __shared__ float gsm[64];

    float wreg[64];
    {
        const float* W = Whh_layer + ((size_t)dir * 1024 + grow) * 256 + kq * 64;
#pragma unroll
        for (int i = 0; i < 16; i++) {
            float4 w4 = *reinterpret_cast<const float4*>(W + i * 4);
            wreg[i * 4 + 0] = w4.x; wreg[i * 4 + 1] = w4.y;
            wreg[i * 4 + 2] = w4.z; wreg[i * 4 + 3] = w4.w;
        }
    }
    const float* xp = g_scratch + OFF_XPROJ + (size_t)dir * 64 * 1024;
    volatile unsigned int* cnt = &g_lstm_cnt[layer][dir];
    float c = 0.0f;

    for (int t = 0; t < 64; t++) {
        const int time = dir ? (63 - t) : t;
        if (tid == 0) {
            const unsigned int need = 16u * (unsigned)t;
            while (*cnt < need) __nanosleep(20);
        }
        __syncthreads();
        {
            volatile float* hb = &g_hbuf[layer][dir][(t + 1) & 1][0];
            hsh[tid] = hb[tid];
        }
        __syncthreads();

        float s = 0.0f;
        const float* hp = &hsh[kq * 64];
#pragma unroll
        for (int i = 0; i < 64; i += 4) {
            s += wreg[i] * hp[i] + wreg[i + 1] * hp[i + 1]
               + wreg[i + 2] * hp[i + 2] + wreg[i + 3] * hp[i + 3];
        }
        s += __shfl_xor_sync(0xffffffffu, s, 1);
        s += __shfl_xor_sync(0xffffffffu, s, 2);
        if (kq == 0) gsm[r] = s + xp[time * 1024 + grow];
        __syncthreads();

        if (tid < 16) {
            float ig = sigmoidf_(gsm[tid]);
            float fg = sigmoidf_(gsm[16 + tid]);
            float gg = tanhf(gsm[32 + tid]);
            float og = sigmoidf_(gsm[48 + tid]);
            c = fg * c + ig * gg;
            float h = og * tanhf(c);
            const int hidx = b * 16 + tid;
            g_hbuf[layer][dir][t & 1][hidx] = h;
            out[time * 512 + dir * 256 + hidx] = h;
        }
        __syncthreads();
        if (tid == 0) {
            __threadfence();
            atomicAdd(&g_lstm_cnt[layer][dir], 1u);
        }
        __syncthreads();
    }
}

// ---------------- final output assembly ----------------
__global__ __launch_bounds__(256) void final_kernel(const int* __restrict__ mnum,
                                                    float* __restrict__ out)
{
    const int i = blockIdx.x * 256 + threadIdx.x;
    const int A = N_NOTES * 1536;
    const float* h1 = g_scratch + OFF_H1;
    const float* h2 = g_scratch + OFF_H;
    const float* mh = g_scratch + OFF_XB2;
    if (i < A) {
        const int n = i / 1536, c = i % 1536;
        float v;
        if (c < 512) {
            int m = mnum[n] - mnum[0];
            v = mh[m * 512 + c];
        } else if (c < 768) {
            v = h1[(size_t)n * GSIZE + c];
        } else {
            v = h2[(size_t)n * GSIZE + (c - 768)];
        }
        out[i] = v;
    } else if (i < A + N_MEAS * 512) {
        out[i] = mh[i - A];
    }
}

// ---------------- host orchestration ----------------
extern "C" void kernel_launch(void* const* d_in, const int* in_sizes, int n_in,
                              void* d_out, int out_size)
{
    const float* nodes = (const float*)d_in[0];
    const float* adj   = (const float*)d_in[1];
    const float* fc_W  = (const float*)d_in[2];
    const float* fc_b  = (const float*)d_in[3];
    const float* g1w   = (const float*)d_in[4];
    const float* g1u   = (const float*)d_in[5];
    const float* g1b   = (const float*)d_in[6];
    const float *gbW, *gbb, *g2w, *g2u, *g2b;
    if (in_sizes[7] == 589824) {
        gbW = (const float*)d_in[7];  gbb = (const float*)d_in[8];
        g2w = (const float*)d_in[9];  g2u = (const float*)d_in[10]; g2b = (const float*)d_in[11];
    } else {
        g2w = (const float*)d_in[7];  g2u = (const float*)d_in[8];  g2b = (const float*)d_in[9];
        gbW = (const float*)d_in[10]; gbb = (const float*)d_in[11];
    }
    const float* attW  = (const float*)d_in[12];
    const float* attb  = (const float*)d_in[13];
    const float* attcv = (const float*)d_in[14];
    const float* Wih   = (const float*)d_in[15];
    const float* Whh   = (const float*)d_in[16];
    const float* bih   = (const float*)d_in[17];
    const float* bhh   = (const float*)d_in[18];
    const int*   mnum  = (const int*)d_in[19];

    float* S = nullptr;
    cudaGetSymbolAddress((void**)&S, g_scratch);
    float* out = (float*)d_out;

    __nv_bfloat16* ACT_H = reinterpret_cast<__nv_bfloat16*>(S + OFF_ACT_H);
    __nv_bfloat16* ACT_L = reinterpret_cast<__nv_bfloat16*>(S + OFF_ACT_L);
    __nv_bfloat16* HR_H  = reinterpret_cast<__nv_bfloat16*>(S + OFF_HR_H);
    __nv_bfloat16* HR_L  = reinterpret_cast<__nv_bfloat16*>(S + OFF_HR_L);
    __nv_bfloat16* RH_H  = reinterpret_cast<__nv_bfloat16*>(S + OFF_RH_H);
    __nv_bfloat16* RH_L  = reinterpret_cast<__nv_bfloat16*>(S + OFF_RH_L);
    __nv_bfloat16* WTC_H = reinterpret_cast<__nv_bfloat16*>(S + OFF_WTC_H);
    __nv_bfloat16* WTC_L = reinterpret_cast<__nv_bfloat16*>(S + OFF_WTC_L);

    cudaFuncSetAttribute(gemm_bf16s_kernel,
                         cudaFuncAttributeMaxDynamicSharedMemorySize, GEMM_SMEM);

    // input-only preprocessing, all up front
    transpose_wu_kernel<<<dim3(24, 24, 54), dim3(32, 8)>>>(g1w, g2w, g1u, g2u);
    build_adj_kernel<<<dim3(4, 8), 256>>>(adj);
    misc_init_kernel<<<16, 256>>>(bih, bhh);

    cudaMemsetAsync(S + OFF_H, 0, (size_t)N_NOTES * GSIZE * sizeof(float), 0);
    cudaMemsetAsync(HR_H, 0, (size_t)N_NOTES * GSIZE * sizeof(__nv_bfloat16), 0);
    cudaMemsetAsync(HR_L, 0, (size_t)N_NOTES * GSIZE * sizeof(__nv_bfloat16), 0);
    gemm_nt_kernel<<<dim3(2, 8), 256>>>(nodes, IN_SIZE, 0, fc_W, 0, fc_b, 0,
                                        S + OFF_H + 512, GSIZE, 0, HR_H + 512, HR_L + 512,
                                        N_NOTES, NOTE_H, IN_SIZE, /*relu*/1);

    auto run_graph = [&](int set, const float* b) {
        __nv_bfloat16* WT_H = reinterpret_cast<__nv_bfloat16*>(S + (set ? OFF_WT2_H : OFF_WT_H));
        __nv_bfloat16* WT_L = reinterpret_cast<__nv_bfloat16*>(S + (set ? OFF_WT2_L : OFF_WT_L));
        __nv_bfloat16* UT_H = reinterpret_cast<__nv_bfloat16*>(S + (set ? OFF_UT2_H : OFF_UT_H));
        __nv_bfloat16* UT_L = reinterpret_cast<__nv_bfloat16*>(S + (set ? OFF_UT2_L : OFF_UT_L));
        for (int it = 0; it < 2; it++) {
            const bool sparse = (set == 0) && (it == 0);   // h has 512 leading zero cols
            if (sparse) {
                act_gather_compact_kernel<<<N_NOTES, 256>>>();
                gemm_bf16s_kernel<<<dim3(6, 8, 3), 256, GEMM_SMEM>>>(
                    ACT_H, ACT_L, KGATE_C,
                    WTC_H, WTC_L, (long)GSIZE * KGATE_C, KGATE_C,
                    HR_H + 512, HR_L + 512, GSIZE,
                    UT_H + 512, UT_L + 512, (long)GSIZE * GSIZE, GSIZE, /*zA2limit*/2,
                    S + OFF_G, (long)N_NOTES * GSIZE, GSIZE,
                    KGATE_C, 256, /*beta*/0,
                    nullptr, nullptr, nullptr, nullptr);
                ew1_kernel<<<3072, 256>>>(b);
                // G2 += rh[:,512:] @ uT[2][512:,:], fused ew2 epilogue
                gemm_bf16s_kernel<<<dim3(6, 8, 1), 256, GEMM_SMEM>>>(
                    RH_H + 512, RH_L + 512, GSIZE,
                    UT_H + (size_t)2 * GSIZE * GSIZE + 512,
                    UT_L + (size_t)2 * GSIZE * GSIZE + 512, 0, GSIZE,
                    nullptr, nullptr, 0, nullptr, nullptr, 0, 0, 0,
                    S + OFF_G + 2u * N_NOTES * GSIZE, 0, GSIZE,
                    256, 0, /*beta*/1,
                    b + 2 * GSIZE, S + OFF_H, HR_H, HR_L);
            } else {
                act_gather_kernel<<<N_NOTES, 256>>>();
                gemm_bf16s_kernel<<<dim3(6, 8, 3), 256, GEMM_SMEM>>>(
                    ACT_H, ACT_L, KGATE,
                    WT_H, WT_L, (long)GSIZE * KGATE, KGATE,
                    HR_H, HR_L, GSIZE,
                    UT_H, UT_L, (long)GSIZE * GSIZE, GSIZE, /*zA2limit*/2,
                    S + OFF_G, (long)N_NOTES * GSIZE, GSIZE,
                    KGATE, GSIZE, /*beta*/0,
                    nullptr, nullptr, nullptr, nullptr);
                ew1_kernel<<<3072, 256>>>(b);
                gemm_bf16s_kernel<<<dim3(6, 8, 1), 256, GEMM_SMEM>>>(
                    RH_H, RH_L, GSIZE,
                    UT_H + (size_t)2 * GSIZE * GSIZE, UT_L + (size_t)2 * GSIZE * GSIZE, 0, GSIZE,
                    nullptr, nullptr, 0, nullptr, nullptr, 0, 0, 0,
                    S + OFF_G + 2u * N_NOTES * GSIZE, 0, GSIZE,
                    GSIZE, 0, /*beta*/1,
                    b + 2 * GSIZE, S + OFF_H, HR_H, HR_L);
            }
        }
    };

    run_graph(0, g1b);
    cudaMemcpyAsync(S + OFF_H1, S + OFF_H, (size_t)N_NOTES * GSIZE * sizeof(float),
                    cudaMemcpyDeviceToDevice, 0);
    gemm_nt_kernel<<<dim3(6, 8), 256>>>(S + OFF_H1, GSIZE, 0, gbW, 0, gbb, 0,
                                        S + OFF_H, GSIZE, 0, HR_H, HR_L,
                                        N_NOTES, GSIZE, GSIZE, /*relu*/1);
    run_graph(1, g2b);

    cat_kernel<<<N_NOTES, 512>>>();
    gemm_nt_kernel<<<dim3(4, 8), 256>>>(S + OFF_CAT, ATT_D, 0, attW, 0, attb, 0,
                                        S + OFF_A, ATT_D, 0, nullptr, nullptr,
                                        N_NOTES, ATT_D, ATT_D, /*tanh*/2);
    att_pool_kernel<<<N_MEAS, 256>>>(attcv, mnum);

    const float* xin = S + OFF_MN;
    for (int l = 0; l < 2; l++) {
        gemm_nt_kernel<<<dim3(8, 1, 2), 256>>>(
            xin, 512, 0,
            Wih + (size_t)l * 2 * 1024 * 512, (long)1024 * 512,
            S + OFF_SB + l * 2 * 1024, 1024,
            S + OFF_XPROJ, 1024, (long)64 * 1024, nullptr, nullptr,
            64, 1024, 512, /*none*/0);
        float* xo = (l == 0) ? (S + OFF_XB1) : (S + OFF_XB2);
        lstm_rec_kernel<<<dim3(16, 2), 256>>>(Whh + (size_t)l * 2 * 1024 * 256, xo, l);
        xin = xo;
    }

    const int total = N_NOTES * 1536 + N_MEAS * 512;
    final_kernel<<<(total + 255) / 256, 256>>>(mnum, out);
}

// round 16
// speedup vs baseline: 1.5463x; 1.5463x over previous
#include <cuda_runtime.h>
#include <cuda_bf16.h>
#include <cstdint>
#include <cstdio>

// ---------------- static config ----------------
#define N_NOTES 1024
#define IN_SIZE 78
#define NOTE_H 256
#define MEAS_H 256
#define GSIZE 768
#define N_EDGE 8
#define N_HEAD 8
#define ATT_D 512
#define N_MEAS 64
#define KGATE 6144   // N_EDGE * GSIZE
#define KGATE_C 2048 // N_EDGE * 256 (compacted, g1-it1)
#define ADJ_CAP 96

// ---------------- scratch (device global; no allocs allowed) ----------------
#define OFF_H      0u
#define OFF_H1     786432u
#define OFF_G      1572864u
#define OFF_Z      3932160u
#define OFF_CAT    4718592u
#define OFF_A      5242880u
#define OFF_MN     5767168u
#define OFF_XPROJ  5799936u
#define OFF_XB1    5931008u
#define OFF_XB2    5963776u
#define OFF_SB     5996544u
#define OFF_ACT_H  6000640u
#define OFF_ACT_L  9146368u
#define OFF_HR_H   12292096u
#define OFF_HR_L   12685312u
#define OFF_RH_H   13078528u
#define OFF_RH_L   13471744u
#define OFF_WT_H   13864960u   // set 0 (g1): wT [3][768][6144]
#define OFF_WT_L   20942848u
#define OFF_UT_H   28020736u   // set 0 (g1): uT [3][768][768]
#define OFF_UT_L   28905472u
#define OFF_WT2_H  29790208u   // set 1 (g2)
#define OFF_WT2_L  36868096u
#define OFF_UT2_H  43945984u
#define OFF_UT2_L  44830720u
#define OFF_WTC_H  45715456u   // compacted wT set0: [3][768][2048]
#define OFF_WTC_L  48074752u
#define SCRATCH_FLOATS 50434048u

__device__ float g_scratch[SCRATCH_FLOATS];
__device__ int g_adj_cnt[N_EDGE * N_NOTES];
__device__ int g_adj_list[N_EDGE * N_NOTES * ADJ_CAP];

// LSTM cross-block sync state (per layer, per dir)
__device__ unsigned int g_lstm_cnt[2][2];
__device__ float g_hbuf[2][2][2][256];   // [layer][dir][parity][256]

__device__ __forceinline__ float sigmoidf_(float x) { return 1.0f / (1.0f + expf(-x)); }

__device__ __forceinline__ void bfsplit(float v, __nv_bfloat16* H, __nv_bfloat16* L, size_t idx) {
    __nv_bfloat16 h = __float2bfloat16(v);
    H[idx] = h;
    L[idx] = __float2bfloat16(v - __bfloat162float(h));
}

// ---- packed f32x2 helpers (fp32 FFMA2 path for NT gemms) ----
__device__ __forceinline__ unsigned long long pack2(float x, float y) {
    unsigned long long r;
    asm("mov.b64 %0, {%1, %2};" : "=l"(r) : "r"(__float_as_uint(x)), "r"(__float_as_uint(y)));
    return r;
}
__device__ __forceinline__ float2 unpack2(unsigned long long v) {
    unsigned int lo, hi;
    asm("mov.b64 {%0, %1}, %2;" : "=r"(lo), "=r"(hi) : "l"(v));
    return make_float2(__uint_as_float(lo), __uint_as_float(hi));
}
#define FFMA2(d, a, b) asm("fma.rn.f32x2 %0, %1, %2, %0;" : "+l"(d) : "l"(a), "l"(b))

// ---- tensor-core helpers (legacy mma.sync — tcgen05 unavailable at compute_103) ----
#define MMA_BF16(d, a, b0, b1) asm volatile( \
    "mma.sync.aligned.m16n8k16.row.col.f32.bf16.bf16.f32 " \
    "{%0,%1,%2,%3}, {%4,%5,%6,%7}, {%8,%9}, {%0,%1,%2,%3};" \
    : "+f"((d)[0]), "+f"((d)[1]), "+f"((d)[2]), "+f"((d)[3]) \
    : "r"((a)[0]), "r"((a)[1]), "r"((a)[2]), "r"((a)[3]), "r"(b0), "r"(b1))

#define LDSM4(r, addr) asm volatile( \
    "ldmatrix.sync.aligned.m8n8.x4.shared.b16 {%0,%1,%2,%3}, [%4];" \
    : "=r"((r)[0]), "=r"((r)[1]), "=r"((r)[2]), "=r"((r)[3]) : "r"(addr))

#define CP16(dst, src) asm volatile( \
    "cp.async.ca.shared.global [%0], [%1], 16;" :: "r"(dst), "l"(src))
#define CP_COMMIT() asm volatile("cp.async.commit_group;")
#define CP_WAIT2()  asm volatile("cp.async.wait_group 2;")
#define CP_WAIT0()  asm volatile("cp.async.wait_group 0;")

// ================= bf16-split tensor GEMM (128x128 tile, 4-stage) — R13 exact ==========
#define BPITCH 40
#define STG_BF (128 * BPITCH)
#define NSTAGE 4
#define GEMM_SMEM (NSTAGE * 4 * STG_BF * 2)   // 163840 bytes

__global__ __launch_bounds__(256) void gemm_bf16s_kernel(
    const __nv_bfloat16* __restrict__ A1h, const __nv_bfloat16* __restrict__ A1l, int lda1,
    const __nv_bfloat16* __restrict__ B1h, const __nv_bfloat16* __restrict__ B1l,
    long b1stride, int ldb1,
    const __nv_bfloat16* __restrict__ A2h, const __nv_bfloat16* __restrict__ A2l, int lda2,
    const __nv_bfloat16* __restrict__ B2h, const __nv_bfloat16* __restrict__ B2l,
    long b2stride, int ldb2, int zA2limit,
    float* __restrict__ Cbase, long cstride, int ldc,
    int K1, int K2, int beta)
{
    extern __shared__ __nv_bfloat16 smb[];
    const int tid = threadIdx.x, lane = tid & 31, wid = tid >> 5;
    const int z = blockIdx.z;
    const int row0 = blockIdx.y * 128, col0 = blockIdx.x * 128;
    const int m0 = (wid >> 1) * 32, n0w = (wid & 1) * 64;
    float* C = Cbase + (long)z * cstride;
    const bool use2 = (z < zA2limit) && (K2 > 0);

    float acc[2][8][4];
#pragma unroll
    for (int i = 0; i < 2; i++)
#pragma unroll
        for (int j = 0; j < 8; j++)
#pragma unroll
            for (int k = 0; k < 4; k++) acc[i][j][k] = 0.0f;

    const uint32_t smu = (uint32_t)__cvta_generic_to_shared(smb);

    const int srow = tid >> 1;
    const int skoff = (tid & 1) * 16;

    const int lRow = lane & 15;
    const int lOff8 = ((lane >> 4) & 1) * 8;

    auto pipeline = [&](const __nv_bfloat16* Ah, const __nv_bfloat16* Al, int lda,
                        const __nv_bfloat16* Bh, const __nv_bfloat16* Bl, int ldb, int K) {
        const int ns = K >> 5;
        auto copy_stage = [&](int st, int kpos) {
            const __nv_bfloat16* sAh = Ah + (size_t)(row0 + srow) * lda + kpos + skoff;
            const __nv_bfloat16* sAl = Al + (size_t)(row0 + srow) * lda + kpos + skoff;
            const __nv_bfloat16* sBh = Bh + (size_t)(col0 + srow) * ldb + kpos + skoff;
            const __nv_bfloat16* sBl = Bl + (size_t)(col0 + srow) * ldb + kpos + skoff;
            const uint32_t rb = (uint32_t)(srow * BPITCH + skoff) * 2;
            uint32_t d0 = smu + (uint32_t)((st * 4 + 0) * STG_BF * 2) + rb;
            uint32_t d1 = smu + (uint32_t)((st * 4 + 1) * STG_BF * 2) + rb;
            uint32_t d2 = smu + (uint32_t)((st * 4 + 2) * STG_BF * 2) + rb;
            uint32_t d3 = smu + (uint32_t)((st * 4 + 3) * STG_BF * 2) + rb;
            CP16(d0, sAh); CP16(d0 + 16, sAh + 8);
            CP16(d1, sAl); CP16(d1 + 16, sAl + 8);
            CP16(d2, sBh); CP16(d2 + 16, sBh + 8);
            CP16(d3, sBl); CP16(d3 + 16, sBl + 8);
        };
        copy_stage(0, 0); CP_COMMIT();
        if (ns > 1) copy_stage(1, 32);
        CP_COMMIT();
        for (int s = 0; s < ns; s++) {
            if (s + 2 < ns) copy_stage((s + 2) & (NSTAGE - 1), (s + 2) * 32);
            CP_COMMIT();
            CP_WAIT2();
            __syncthreads();
            const int st = s & (NSTAGE - 1);
            const uint32_t aH = smu + (uint32_t)((st * 4 + 0) * STG_BF * 2);
            const uint32_t aL = smu + (uint32_t)((st * 4 + 1) * STG_BF * 2);
            const uint32_t bH = smu + (uint32_t)((st * 4 + 2) * STG_BF * 2);
            const uint32_t bL = smu + (uint32_t)((st * 4 + 3) * STG_BF * 2);
#pragma unroll
            for (int kh = 0; kh < 32; kh += 16) {
                uint32_t afh[2][4], afl[2][4];
#pragma unroll
                for (int mt = 0; mt < 2; mt++) {
                    const uint32_t off =
                        (uint32_t)(((m0 + mt * 16 + lRow) * BPITCH + kh + lOff8) * 2);
                    LDSM4(afh[mt], aH + off);
                    LDSM4(afl[mt], aL + off);
                }
                uint32_t bfh[4][4], bfl[4][4];
#pragma unroll
                for (int q = 0; q < 4; q++) {
                    const uint32_t off =
                        (uint32_t)(((n0w + q * 16 + lRow) * BPITCH + kh + lOff8) * 2);
                    LDSM4(bfh[q], bH + off);
                    LDSM4(bfl[q], bL + off);
                }
#pragma unroll
                for (int mt = 0; mt < 2; mt++)
#pragma unroll
                    for (int q = 0; q < 4; q++) {
                        MMA_BF16(acc[mt][2 * q], afl[mt], bfh[q][0], bfh[q][2]);
                        MMA_BF16(acc[mt][2 * q], afh[mt], bfl[q][0], bfl[q][2]);
                        MMA_BF16(acc[mt][2 * q], afh[mt], bfh[q][0], bfh[q][2]);
                        MMA_BF16(acc[mt][2 * q + 1], afl[mt], bfh[q][1], bfh[q][3]);
                        MMA_BF16(acc[mt][2 * q + 1], afh[mt], bfl[q][1], bfl[q][3]);
                        MMA_BF16(acc[mt][2 * q + 1], afh[mt], bfh[q][1], bfh[q][3]);
                    }
            }
            __syncthreads();
        }
        CP_WAIT0();
        __syncthreads();
    };

    pipeline(A1h, A1l, lda1, B1h + (long)z * b1stride, B1l + (long)z * b1stride, ldb1, K1);
    if (use2)
        pipeline(A2h, A2l, lda2, B2h + (long)z * b2stride, B2l + (long)z * b2stride, ldb2, K2);

    const int r = lane >> 2, cb = 2 * (lane & 3);
#pragma unroll
    for (int mt = 0; mt < 2; mt++)
#pragma unroll
        for (int nt = 0; nt < 8; nt++) {
            const int col = col0 + n0w + nt * 8 + cb;
            float* p0 = C + (size_t)(row0 + m0 + mt * 16 + r) * ldc + col;
            float* p1 = C + (size_t)(row0 + m0 + mt * 16 + r + 8) * ldc + col;
            float2 v0 = make_float2(acc[mt][nt][0], acc[mt][nt][1]);
            float2 v1 = make_float2(acc[mt][nt][2], acc[mt][nt][3]);
            if (beta) {
                float2 o0 = *reinterpret_cast<float2*>(p0);
                float2 o1 = *reinterpret_cast<float2*>(p1);
                v0.x += o0.x; v0.y += o0.y; v1.x += o1.x; v1.y += o1.y;
            }
            *reinterpret_cast<float2*>(p0) = v0;
            *reinterpret_cast<float2*>(p1) = v1;
        }
}

// ---------------- merged transposes (bf16-split): w slabs (z<48) + u slabs ----------------
__global__ __launch_bounds__(256) void transpose_wu_kernel(
    const float* __restrict__ w1, const float* __restrict__ w2,
    const float* __restrict__ u1, const float* __restrict__ u2)
{
    __shared__ float t[32][33];
    const int zz = blockIdx.z;
    const int s0 = blockIdx.y * 32, n0 = blockIdx.x * 32;
    const int tx = threadIdx.x, ty = threadIdx.y;

    if (zz < 48) {
        const int set = zz / 24, zr = zz % 24;
        const float* w = set ? w2 : w1;
        const int g = zr >> 3, e = zr & 7;
        const float* src = w + ((size_t)(g * 8 + e) * 768 + s0) * 768 + n0;
#pragma unroll
        for (int i = 0; i < 32; i += 8) t[ty + i][tx] = src[(size_t)(ty + i) * 768 + tx];
        __syncthreads();
        __nv_bfloat16* H = reinterpret_cast<__nv_bfloat16*>(g_scratch + (set ? OFF_WT2_H : OFF_WT_H));
        __nv_bfloat16* L = reinterpret_cast<__nv_bfloat16*>(g_scratch + (set ? OFF_WT2_L : OFF_WT_L));
        __nv_bfloat16* HC = reinterpret_cast<__nv_bfloat16*>(g_scratch + OFF_WTC_H);
        __nv_bfloat16* LC = reinterpret_cast<__nv_bfloat16*>(g_scratch + OFF_WTC_L);
        const size_t base = (size_t)g * 768 * 6144 + (size_t)n0 * 6144 + e * 768 + s0;
        const bool compact = (set == 0) && (s0 >= 512);
        const size_t cbase = (size_t)g * 768 * KGATE_C + (size_t)n0 * KGATE_C + e * 256 + (s0 - 512);
#pragma unroll
        for (int i = 0; i < 32; i += 8) {
            float v = t[tx][ty + i];
            bfsplit(v, H, L, base + (size_t)(ty + i) * 6144 + tx);
            if (compact)
                bfsplit(v, HC, LC, cbase + (size_t)(ty + i) * KGATE_C + tx);
        }
    } else {
        const int zu = zz - 48;
        const int set = zu / 3, g = zu % 3;
        const float* u = set ? u2 : u1;
        const float* src = u + ((size_t)g * 768 + s0) * 768 + n0;
#pragma unroll
        for (int i = 0; i < 32; i += 8) t[ty + i][tx] = src[(size_t)(ty + i) * 768 + tx];
        __syncthreads();
        __nv_bfloat16* H = reinterpret_cast<__nv_bfloat16*>(g_scratch + (set ? OFF_UT2_H : OFF_UT_H));
        __nv_bfloat16* L = reinterpret_cast<__nv_bfloat16*>(g_scratch + (set ? OFF_UT2_L : OFF_UT_L));
        const size_t base = (size_t)g * 768 * 768 + (size_t)n0 * 768 + s0;
#pragma unroll
        for (int i = 0; i < 32; i += 8)
            bfsplit(t[tx][ty + i], H, L, base + (size_t)(ty + i) * 768 + tx);
    }
}

// ---------------- GEMM NT (C = act(A @ B^T + bias)), fp32 FFMA2, z-batched ----------------
__global__ __launch_bounds__(256) void gemm_nt_kernel(
    const float* __restrict__ Abase, int lda, long aBS,
    const float* __restrict__ Bbase, long bBS,
    const float* __restrict__ biasbase, long biasBS,
    float* __restrict__ Cbase, int ldc, long cBS,
    __nv_bfloat16* __restrict__ CrH, __nv_bfloat16* __restrict__ CrL,
    int M, int N, int K, int act)
{
    const int tid = threadIdx.x;
    const int z = blockIdx.z;
    const float* A = Abase + (long)z * aBS;
    const float* B = Bbase + (long)z * bBS;
    const float* bias = biasbase + (long)z * biasBS;
    float* C = Cbase + (long)z * cBS;

    __shared__ float As[8][128];
    __shared__ float Bs[8][128];

    const int row0 = blockIdx.y * 128;
    const int col0 = blockIdx.x * 128;
    const int tx = tid & 15, ty = tid >> 4;
    const int arow = tid >> 1, ak = (tid & 1) * 4;
    const int bnr = tid >> 1, bk = (tid & 1) * 4;

    unsigned long long acc[2][2][8];
#pragma unroll
    for (int h = 0; h < 2; h++)
#pragma unroll
        for (int p = 0; p < 2; p++)
#pragma unroll
            for (int c = 0; c < 8; c++) acc[h][p][c] = 0ULL;

    for (int k0 = 0; k0 < K; k0 += 8) {
        const int garow = row0 + arow;
#pragma unroll
        for (int t = 0; t < 4; t++) {
            int k = k0 + ak + t;
            As[ak + t][arow] = (garow < M && k < K) ? A[(size_t)garow * lda + k] : 0.0f;
        }
#pragma unroll
        for (int t = 0; t < 4; t++) {
            int k = k0 + bk + t;
            Bs[bk + t][bnr] = (k < K) ? B[(size_t)(col0 + bnr) * K + k] : 0.0f;
        }
        __syncthreads();
#pragma unroll
        for (int kk = 0; kk < 8; kk++) {
            ulonglong2 a0 = *reinterpret_cast<ulonglong2*>(&As[kk][ty * 4]);
            ulonglong2 a1 = *reinterpret_cast<ulonglong2*>(&As[kk][64 + ty * 4]);
            float4 blo = *reinterpret_cast<float4*>(&Bs[kk][tx * 4]);
            float4 bhi = *reinterpret_cast<float4*>(&Bs[kk][64 + tx * 4]);
            unsigned long long bb[8];
            bb[0] = pack2(blo.x, blo.x); bb[1] = pack2(blo.y, blo.y);
            bb[2] = pack2(blo.z, blo.z); bb[3] = pack2(blo.w, blo.w);
            bb[4] = pack2(bhi.x, bhi.x); bb[5] = pack2(bhi.y, bhi.y);
            bb[6] = pack2(bhi.z, bhi.z); bb[7] = pack2(bhi.w, bhi.w);
#pragma unroll
            for (int c = 0; c < 8; c++) {
                FFMA2(acc[0][0][c], a0.x, bb[c]);
                FFMA2(acc[0][1][c], a0.y, bb[c]);
                FFMA2(acc[1][0][c], a1.x, bb[c]);
                FFMA2(acc[1][1][c], a1.y, bb[c]);
            }
        }
        __syncthreads();
    }

#pragma unroll
    for (int hr = 0; hr < 2; hr++)
#pragma unroll
        for (int pr = 0; pr < 2; pr++)
#pragma unroll
            for (int sub = 0; sub < 2; sub++) {
                const int row = row0 + hr * 64 + ty * 4 + pr * 2 + sub;
                if (row >= M) continue;
#pragma unroll
                for (int half = 0; half < 2; half++) {
                    const int colb = col0 + half * 64 + tx * 4;
                    float* cp = C + (size_t)row * ldc + colb;
#pragma unroll
                    for (int c = 0; c < 4; c++) {
                        float2 f2 = unpack2(acc[hr][pr][half * 4 + c]);
                        float v = (sub ? f2.y : f2.x) + bias[colb + c];
                        if (act == 1) v = fmaxf(v, 0.0f);
                        else if (act == 2) v = tanhf(v);
                        cp[c] = v;
                        if (CrH) bfsplit(v, CrH, CrL, (size_t)row * ldc + colb + c);
                    }
                }
            }
}

// ---------------- adjacency CSR precompute ----------------
__global__ __launch_bounds__(256) void build_adj_kernel(const float* __restrict__ A)
{
    const int n = blockIdx.x * 256 + threadIdx.x;
    const int e = blockIdx.y;
    const float* col = A + (size_t)e * N_NOTES * N_NOTES + n;
    int cnt = 0;
    int* list = g_adj_list + ((size_t)e * N_NOTES + n) * ADJ_CAP;
#pragma unroll 8
    for (int m = 0; m < N_NOTES; m++) {
        float v = col[(size_t)m * N_NOTES];
        if (v != 0.0f) { if (cnt < ADJ_CAP) list[cnt] = m; cnt++; }
    }
    g_adj_cnt[e * N_NOTES + n] = min(cnt, ADJ_CAP);
}

// ---------------- sparse act (bf16-split output), full width ----------------
__global__ __launch_bounds__(256) void act_gather_kernel()
{
    const int n = blockIdx.x;
    const int tid = threadIdx.x;
    const float* h = g_scratch + OFF_H;
    __nv_bfloat16* AH = reinterpret_cast<__nv_bfloat16*>(g_scratch + OFF_ACT_H);
    __nv_bfloat16* AL = reinterpret_cast<__nv_bfloat16*>(g_scratch + OFF_ACT_L);
    const size_t base = (size_t)n * KGATE;
    __shared__ int lst[ADJ_CAP];
    for (int e = 0; e < N_EDGE; e++) {
        const int cnt = g_adj_cnt[e * N_NOTES + n];
        if (tid < cnt) lst[tid] = g_adj_list[((size_t)e * N_NOTES + n) * ADJ_CAP + tid];
        __syncthreads();
        float a0 = 0.f, a1 = 0.f, a2 = 0.f;
        for (int i = 0; i < cnt; i++) {
            const float* hr = h + (size_t)lst[i] * GSIZE;
            a0 += hr[tid]; a1 += hr[tid + 256]; a2 += hr[tid + 512];
        }
        bfsplit(a0, AH, AL, base + e * GSIZE + tid);
        bfsplit(a1, AH, AL, base + e * GSIZE + 256 + tid);
        bfsplit(a2, AH, AL, base + e * GSIZE + 512 + tid);
        __syncthreads();
    }
}

// compacted variant for g1-it1: only h cols [512,768) are nonzero; writes [1024][2048]
__global__ __launch_bounds__(256) void act_gather_compact_kernel()
{
    const int n = blockIdx.x;
    const int tid = threadIdx.x;
    const float* h = g_scratch + OFF_H;
    __nv_bfloat16* AH = reinterpret_cast<__nv_bfloat16*>(g_scratch + OFF_ACT_H);
    __nv_bfloat16* AL = reinterpret_cast<__nv_bfloat16*>(g_scratch + OFF_ACT_L);
    const size_t base = (size_t)n * KGATE_C;
    __shared__ int lst[ADJ_CAP];
    for (int e = 0; e < N_EDGE; e++) {
        const int cnt = g_adj_cnt[e * N_NOTES + n];
        if (tid < cnt) lst[tid] = g_adj_list[((size_t)e * N_NOTES + n) * ADJ_CAP + tid];
        __syncthreads();
        float a = 0.f;
        for (int i = 0; i < cnt; i++)
            a += h[(size_t)lst[i] * GSIZE + 512 + tid];
        bfsplit(a, AH, AL, base + e * 256 + tid);
        __syncthreads();
    }
}

// ---------------- gated-graph elementwise ----------------
__global__ __launch_bounds__(256) void ew1_kernel(const float* __restrict__ b)
{
    const int i = blockIdx.x * 256 + threadIdx.x;
    const int s = i % GSIZE;
    const float* G = g_scratch + OFF_G;
    const float* h = g_scratch + OFF_H;
    float zz = sigmoidf_(G[i] + b[s]);
    float rr = sigmoidf_(G[N_NOTES * GSIZE + i] + b[GSIZE + s]);
    g_scratch[OFF_Z + i] = zz;
    bfsplit(rr * h[i],
            reinterpret_cast<__nv_bfloat16*>(g_scratch + OFF_RH_H),
            reinterpret_cast<__nv_bfloat16*>(g_scratch + OFF_RH_L), i);
}

// ew2; optionally duplicates h into h1dup (last g1 iteration), replacing the D2D memcpy
__global__ __launch_bounds__(256) void ew2_kernel(const float* __restrict__ b2,
                                                  float* __restrict__ h1dup)
{
    const int i = blockIdx.x * 256 + threadIdx.x;
    const int s = i % GSIZE;
    const float* G2 = g_scratch + OFF_G + 2u * N_NOTES * GSIZE;
    float ht = tanhf(G2[i] + b2[s]);
    float zz = g_scratch[OFF_Z + i];
    float* h = g_scratch + OFF_H;
    float v = zz * h[i] + (1.0f - zz) * ht;
    h[i] = v;
    if (h1dup) h1dup[i] = v;
    bfsplit(v,
            reinterpret_cast<__nv_bfloat16*>(g_scratch + OFF_HR_H),
            reinterpret_cast<__nv_bfloat16*>(g_scratch + OFF_HR_L), i);
}

// ---------------- cat = [h1[:,512:768] | h2[:,512:768]] ----------------
__global__ __launch_bounds__(512) void cat_kernel()
{
    const int n = blockIdx.x, c = threadIdx.x;
    const float* h1 = g_scratch + OFF_H1;
    const float* h2 = g_scratch + OFF_H;
    g_scratch[OFF_CAT + n * ATT_D + c] =
        (c < 256) ? h1[(size_t)n * GSIZE + 512 + c]
                  : h2[(size_t)n * GSIZE + 512 + (c - 256)];
}

// ---------------- measure attention pooling ----------------
__global__ __launch_bounds__(256) void att_pool_kernel(
    const float* __restrict__ cv, const int* __restrict__ mnum)
{
    const int m = blockIdx.x;
    const int tid = threadIdx.x;
    const float* a = g_scratch + OFF_A;
    const float* x = g_scratch + OFF_CAT;
    __shared__ int list[64];
    __shared__ int cnt;
    __shared__ float s_sh[64][8];
    __shared__ float hmax[8], hden[8];
    if (tid == 0) cnt = 0;
    __syncthreads();
    const int mn0 = mnum[0];
    for (int n = tid; n < N_NOTES; n += 256) {
        if (mnum[n] - mn0 == m) {
            int p = atomicAdd(&cnt, 1);
            if (p < 64) list[p] = n;
        }
    }
    __syncthreads();
    const int c = min(cnt, 64);
    const int w = tid >> 5, lane = tid & 31;
    for (int i = w; i < c; i += 8) {
        const float* ar = a + (size_t)list[i] * ATT_D;
#pragma unroll
        for (int h = 0; h < 8; h++) {
            float p = ar[h * 64 + lane] * cv[h * 64 + lane]
                    + ar[h * 64 + 32 + lane] * cv[h * 64 + 32 + lane];
            p += __shfl_xor_sync(0xffffffffu, p, 16);
            p += __shfl_xor_sync(0xffffffffu, p, 8);
            p += __shfl_xor_sync(0xffffffffu, p, 4);
            p += __shfl_xor_sync(0xffffffffu, p, 2);
            p += __shfl_xor_sync(0xffffffffu, p, 1);
            if (lane == 0) s_sh[i][h] = p;
        }
    }
    __syncthreads();
    if (tid < 8) {
        float mx = -1e30f;
        for (int i = 0; i < c; i++) mx = fmaxf(mx, s_sh[i][tid]);
        float den = 0.f;
        for (int i = 0; i < c; i++) den += expf(s_sh[i][tid] - mx);
        hmax[tid] = mx; hden[tid] = den;
    }
    __syncthreads();
    for (int col = tid; col < ATT_D; col += 256) {
        const int h = col >> 6;
        float pool = 0.f;
        for (int i = 0; i < c; i++) {
            float wgt = expf(s_sh[i][h] - hmax[h]) / hden[h];
            pool += wgt * x[(size_t)list[i] * ATT_D + col];
        }
        g_scratch[OFF_MN + m * ATT_D + col] = pool;
    }
}

// ---------------- misc init: sumbias + LSTM state ----------------
__global__ __launch_bounds__(256) void misc_init_kernel(const float* __restrict__ bih,
                                                        const float* __restrict__ bhh)
{
    const int i = blockIdx.x * 256 + threadIdx.x;
    g_scratch[OFF_SB + i] = bih[i] + bhh[i];
    if (blockIdx.x == 0) {
        if (threadIdx.x < 4) (&g_lstm_cnt[0][0])[threadIdx.x] = 0u;
        float* p = &g_hbuf[0][0][0][0];
        for (int k = threadIdx.x; k < 2048; k += 256) p[k] = 0.0f;
    }
}

__global__ __launch_bounds__(256) void lstm_rec_kernel(
    const float* __restrict__ Whh_layer,   // [2][1024][256]
    float* __restrict__ out, int layer)    // [64][512]
{
    const int b = blockIdx.x;
    const int dir = blockIdx.y;
    const int tid = threadIdx.x;
    const int r = tid >> 2;
    const int kq = tid & 3;
    const int seg = r >> 4, jj = r & 15;
    const int grow = seg * 256 + b * 16 + jj;

    __shared__ float hsh[256];
    __shared__ float gsm[64];

    float wreg[64];
    {
        const float* W = Whh_layer + ((size_t)dir * 1024 + grow) * 256 + kq * 64;
#pragma unroll
        for (int i = 0; i < 16; i++) {
            float4 w4 = *reinterpret_cast<const float4*>(W + i * 4);
            wreg[i * 4 + 0] = w4.x; wreg[i * 4 + 1] = w4.y;
            wreg[i * 4 + 2] = w4.z; wreg[i * 4 + 3] = w4.w;
        }
    }
    const float* xp = g_scratch + OFF_XPROJ + (size_t)dir * 64 * 1024;
    volatile unsigned int* cnt = &g_lstm_cnt[layer][dir];
    float c = 0.0f;

    for (int t = 0; t < 64; t++) {
        const int time = dir ? (63 - t) : t;
        if (tid == 0) {
            const unsigned int need = 16u * (unsigned)t;
            while (*cnt < need) __nanosleep(20);
        }
        __syncthreads();
        {
            volatile float* hb = &g_hbuf[layer][dir][(t + 1) & 1][0];
            hsh[tid] = hb[tid];
        }
        __syncthreads();

        float s = 0.0f;
        const float* hp = &hsh[kq * 64];
#pragma unroll
        for (int i = 0; i < 64; i += 4) {
            s += wreg[i] * hp[i] + wreg[i + 1] * hp[i + 1]
               + wreg[i + 2] * hp[i + 2] + wreg[i + 3] * hp[i + 3];
        }
        s += __shfl_xor_sync(0xffffffffu, s, 1);
        s += __shfl_xor_sync(0xffffffffu, s, 2);
        if (kq == 0) gsm[r] = s + xp[time * 1024 + grow];
        __syncthreads();

        if (tid < 16) {
            float ig = sigmoidf_(gsm[tid]);
            float fg = sigmoidf_(gsm[16 + tid]);
            float gg = tanhf(gsm[32 + tid]);
            float og = sigmoidf_(gsm[48 + tid]);
            c = fg * c + ig * gg;
            float h = og * tanhf(c);
            const int hidx = b * 16 + tid;
            g_hbuf[layer][dir][t & 1][hidx] = h;
            out[time * 512 + dir * 256 + hidx] = h;
        }
        __syncthreads();
        if (tid == 0) {
            __threadfence();
            atomicAdd(&g_lstm_cnt[layer][dir], 1u);
        }
        __syncthreads();
    }
}

// ---------------- final output assembly ----------------
__global__ __launch_bounds__(256) void final_kernel(const int* __restrict__ mnum,
                                                    float* __restrict__ out)
{
    const int i = blockIdx.x * 256 + threadIdx.x;
    const int A = N_NOTES * 1536;
    const float* h1 = g_scratch + OFF_H1;
    const float* h2 = g_scratch + OFF_H;
    const float* mh = g_scratch + OFF_XB2;
    if (i < A) {
        const int n = i / 1536, c = i % 1536;
        float v;
        if (c < 512) {
            int m = mnum[n] - mnum[0];
            v = mh[m * 512 + c];
        } else if (c < 768) {
            v = h1[(size_t)n * GSIZE + c];
        } else {
            v = h2[(size_t)n * GSIZE + (c - 768)];
        }
        out[i] = v;
    } else if (i < A + N_MEAS * 512) {
        out[i] = mh[i - A];
    }
}

// ---------------- host orchestration ----------------
extern "C" void kernel_launch(void* const* d_in, const int* in_sizes, int n_in,
                              void* d_out, int out_size)
{
    const float* nodes = (const float*)d_in[0];
    const float* adj   = (const float*)d_in[1];
    const float* fc_W  = (const float*)d_in[2];
    const float* fc_b  = (const float*)d_in[3];
    const float* g1w   = (const float*)d_in[4];
    const float* g1u   = (const float*)d_in[5];
    const float* g1b   = (const float*)d_in[6];
    const float *gbW, *gbb, *g2w, *g2u, *g2b;
    if (in_sizes[7] == 589824) {
        gbW = (const float*)d_in[7];  gbb = (const float*)d_in[8];
        g2w = (const float*)d_in[9];  g2u = (const float*)d_in[10]; g2b = (const float*)d_in[11];
    } else {
        g2w = (const float*)d_in[7];  g2u = (const float*)d_in[8];  g2b = (const float*)d_in[9];
        gbW = (const float*)d_in[10]; gbb = (const float*)d_in[11];
    }
    const float* attW  = (const float*)d_in[12];
    const float* attb  = (const float*)d_in[13];
    const float* attcv = (const float*)d_in[14];
    const float* Wih   = (const float*)d_in[15];
    const float* Whh   = (const float*)d_in[16];
    const float* bih   = (const float*)d_in[17];
    const float* bhh   = (const float*)d_in[18];
    const int*   mnum  = (const int*)d_in[19];

    float* S = nullptr;
    cudaGetSymbolAddress((void**)&S, g_scratch);
    float* out = (float*)d_out;

    __nv_bfloat16* ACT_H = reinterpret_cast<__nv_bfloat16*>(S + OFF_ACT_H);
    __nv_bfloat16* ACT_L = reinterpret_cast<__nv_bfloat16*>(S + OFF_ACT_L);
    __nv_bfloat16* HR_H  = reinterpret_cast<__nv_bfloat16*>(S + OFF_HR_H);
    __nv_bfloat16* HR_L  = reinterpret_cast<__nv_bfloat16*>(S + OFF_HR_L);
    __nv_bfloat16* RH_H  = reinterpret_cast<__nv_bfloat16*>(S + OFF_RH_H);
    __nv_bfloat16* RH_L  = reinterpret_cast<__nv_bfloat16*>(S + OFF_RH_L);
    __nv_bfloat16* WTC_H = reinterpret_cast<__nv_bfloat16*>(S + OFF_WTC_H);
    __nv_bfloat16* WTC_L = reinterpret_cast<__nv_bfloat16*>(S + OFF_WTC_L);

    cudaFuncSetAttribute(gemm_bf16s_kernel,
                         cudaFuncAttributeMaxDynamicSharedMemorySize, GEMM_SMEM);

    // input-only preprocessing, all up front
    transpose_wu_kernel<<<dim3(24, 24, 54), dim3(32, 8)>>>(g1w, g2w, g1u, g2u);
    build_adj_kernel<<<dim3(4, 8), 256>>>(adj);
    misc_init_kernel<<<16, 256>>>(bih, bhh);

    cudaMemsetAsync(S + OFF_H, 0, (size_t)N_NOTES * GSIZE * sizeof(float), 0);
    cudaMemsetAsync(HR_H, 0, (size_t)N_NOTES * GSIZE * sizeof(__nv_bfloat16), 0);
    cudaMemsetAsync(HR_L, 0, (size_t)N_NOTES * GSIZE * sizeof(__nv_bfloat16), 0);
    gemm_nt_kernel<<<dim3(2, 8), 256>>>(nodes, IN_SIZE, 0, fc_W, 0, fc_b, 0,
                                        S + OFF_H + 512, GSIZE, 0, HR_H + 512, HR_L + 512,
                                        N_NOTES, NOTE_H, IN_SIZE, /*relu*/1);

    auto run_graph = [&](int set, const float* b) {
        __nv_bfloat16* WT_H = reinterpret_cast<__nv_bfloat16*>(S + (set ? OFF_WT2_H : OFF_WT_H));
        __nv_bfloat16* WT_L = reinterpret_cast<__nv_bfloat16*>(S + (set ? OFF_WT2_L : OFF_WT_L));
        __nv_bfloat16* UT_H = reinterpret_cast<__nv_bfloat16*>(S + (set ? OFF_UT2_H : OFF_UT_H));
        __nv_bfloat16* UT_L = reinterpret_cast<__nv_bfloat16*>(S + (set ? OFF_UT2_L : OFF_UT_L));
        for (int it = 0; it < 2; it++) {
            const bool sparse = (set == 0) && (it == 0);   // h has 512 leading zero cols
            if (sparse) {
                act_gather_compact_kernel<<<N_NOTES, 256>>>();
                gemm_bf16s_kernel<<<dim3(6, 8, 3), 256, GEMM_SMEM>>>(
                    ACT_H, ACT_L, KGATE_C,
                    WTC_H, WTC_L, (long)GSIZE * KGATE_C, KGATE_C,
                    HR_H + 512, HR_L + 512, GSIZE,
                    UT_H + 512, UT_L + 512, (long)GSIZE * GSIZE, GSIZE, /*zA2limit*/2,
                    S + OFF_G, (long)N_NOTES * GSIZE, GSIZE,
                    KGATE_C, 256, /*beta*/0);
                ew1_kernel<<<3072, 256>>>(b);
                gemm_bf16s_kernel<<<dim3(6, 8, 1), 256, GEMM_SMEM>>>(
                    RH_H + 512, RH_L + 512, GSIZE,
                    UT_H + (size_t)2 * GSIZE * GSIZE + 512,
                    UT_L + (size_t)2 * GSIZE * GSIZE + 512, 0, GSIZE,
                    nullptr, nullptr, 0, nullptr, nullptr, 0, 0, 0,
                    S + OFF_G + 2u * N_NOTES * GSIZE, 0, GSIZE,
                    256, 0, /*beta*/1);
            } else {
                act_gather_kernel<<<N_NOTES, 256>>>();
                gemm_bf16s_kernel<<<dim3(6, 8, 3), 256, GEMM_SMEM>>>(
                    ACT_H, ACT_L, KGATE,
                    WT_H, WT_L, (long)GSIZE * KGATE, KGATE,
                    HR_H, HR_L, GSIZE,
                    UT_H, UT_L, (long)GSIZE * GSIZE, GSIZE, /*zA2limit*/2,
                    S + OFF_G, (long)N_NOTES * GSIZE, GSIZE,
                    KGATE, GSIZE, /*beta*/0);
                ew1_kernel<<<3072, 256>>>(b);
                gemm_bf16s_kernel<<<dim3(6, 8, 1), 256, GEMM_SMEM>>>(
                    RH_H, RH_L, GSIZE,
                    UT_H + (size_t)2 * GSIZE * GSIZE, UT_L + (size_t)2 * GSIZE * GSIZE, 0, GSIZE,
                    nullptr, nullptr, 0, nullptr, nullptr, 0, 0, 0,
                    S + OFF_G + 2u * N_NOTES * GSIZE, 0, GSIZE,
                    GSIZE, 0, /*beta*/1);
            }
            // last g1 iteration also duplicates h into H1 (replaces D2D memcpy)
            float* h1dup = (set == 0 && it == 1) ? (S + OFF_H1) : nullptr;
            ew2_kernel<<<3072, 256>>>(b + 2 * GSIZE, h1dup);
        }
    };

    run_graph(0, g1b);
    gemm_nt_kernel<<<dim3(6, 8), 256>>>(S + OFF_H1, GSIZE, 0, gbW, 0, gbb, 0,
                                        S + OFF_H, GSIZE, 0, HR_H, HR_L,
                                        N_NOTES, GSIZE, GSIZE, /*relu*/1);
    run_graph(1, g2b);

    cat_kernel<<<N_NOTES, 512>>>();
    gemm_nt_kernel<<<dim3(4, 8), 256>>>(S + OFF_CAT, ATT_D, 0, attW, 0, attb, 0,
                                        S + OFF_A, ATT_D, 0, nullptr, nullptr,
                                        N_NOTES, ATT_D, ATT_D, /*tanh*/2);
    att_pool_kernel<<<N_MEAS, 256>>>(attcv, mnum);

    const float* xin = S + OFF_MN;
    for (int l = 0; l < 2; l++) {
        gemm_nt_kernel<<<dim3(8, 1, 2), 256>>>(
            xin, 512, 0,
            Wih + (size_t)l * 2 * 1024 * 512, (long)1024 * 512,
            S + OFF_SB + l * 2 * 1024, 1024,
            S + OFF_XPROJ, 1024, (long)64 * 1024, nullptr, nullptr,
            64, 1024, 512, /*none*/0);
        float* xo = (l == 0) ? (S + OFF_XB1) : (S + OFF_XB2);
        lstm_rec_kernel<<<dim3(16, 2), 256>>>(Whh + (size_t)l * 2 * 1024 * 256, xo, l);
        xin = xo;
    }

    const int total = N_NOTES * 1536 + N_MEAS * 512;
    final_kernel<<<(total + 255) / 256, 256>>>(mnum, out);
}